// round 2
// baseline (speedup 1.0000x reference)
#include <cuda_runtime.h>
#include <cuda_bf16.h>
#include <math.h>

#define N_NODES 50000
#define N_EDGES 800000
#define NF 128
#define NH 512

// ---------------- scratch (device globals; no cudaMalloc allowed) ----------
__device__ float g_dinv[N_NODES];
__device__ int   g_cnt[N_NODES];
__device__ int   g_rowptr[N_NODES + 1];
__device__ int   g_cursor[N_NODES];
__device__ int   g_col[N_EDGES];
__device__ float g_w[N_EDGES];
__device__ __align__(16) float g_AX[(size_t)N_NODES * NF];   // 25.6 MB
__device__ __align__(16) float g_H[(size_t)N_NODES * NH];    // 102.4 MB
__device__ float2 g_HW2[N_NODES];
__device__ int   g_is32;   // 1 if edge_index arrives as int32, 0 if int64

// ---------------- 0. dtype probe (deterministic every launch) -------------
__global__ void k_probe(const void* __restrict__ ei) {
    if (threadIdx.x == 0 && blockIdx.x == 0) {
        const long long* p = (const long long*)ei;
        int bad = 0;
        for (int i = 0; i < 16; i++) {
            long long v = p[i];
            if (v < 0 || v >= (long long)N_NODES) bad = 1;
        }
        // int64 indices in-range -> bad=0 -> is32=0
        // int32 data read as int64 -> packed pairs are huge -> bad=1 -> is32=1
        g_is32 = bad;
    }
}

__device__ __forceinline__ int clampi(int v) {
    v = v < 0 ? 0 : v;
    return v >= N_NODES ? N_NODES - 1 : v;
}
__device__ __forceinline__ int edge_src(const void* ei, int e) {
    int v = g_is32 ? ((const int*)ei)[e] : (int)((const long long*)ei)[e];
    return clampi(v);
}
__device__ __forceinline__ int edge_dst(const void* ei, int e) {
    int v = g_is32 ? ((const int*)ei)[N_EDGES + e]
                   : (int)((const long long*)ei)[N_EDGES + e];
    return clampi(v);
}

// ---------------- 1. degree / dinv ----------------
__global__ void k_zero_cnt() {
    int i = blockIdx.x * blockDim.x + threadIdx.x;
    if (i < N_NODES) g_cnt[i] = 0;
}

__global__ void k_count(const void* __restrict__ ei) {
    int e = blockIdx.x * blockDim.x + threadIdx.x;
    if (e < N_EDGES) {
        int d = edge_dst(ei, e);
        atomicAdd(&g_cnt[d], 1);
    }
}

__global__ void k_dinv() {
    int i = blockIdx.x * blockDim.x + threadIdx.x;
    if (i < N_NODES) g_dinv[i] = rsqrtf((float)g_cnt[i] + 1.0f);
}

// ---------------- 2. CSR build ----------------
__global__ void k_scan() {
    __shared__ int sums[1024];
    const int tid = threadIdx.x;
    const int CH = (N_NODES + 1023) / 1024;  // 49
    int base = tid * CH;
    int s = 0;
    for (int i = 0; i < CH; i++) {
        int idx = base + i;
        if (idx < N_NODES) s += g_cnt[idx];
    }
    sums[tid] = s;
    __syncthreads();
    for (int off = 1; off < 1024; off <<= 1) {
        int v = (tid >= off) ? sums[tid - off] : 0;
        __syncthreads();
        sums[tid] += v;
        __syncthreads();
    }
    int run = (tid == 0) ? 0 : sums[tid - 1];
    for (int i = 0; i < CH; i++) {
        int idx = base + i;
        if (idx < N_NODES) {
            g_rowptr[idx] = run;
            g_cursor[idx] = run;
            run += g_cnt[idx];
        }
    }
    if (tid == 1023) g_rowptr[N_NODES] = sums[1023];
}

__global__ void k_scatter(const void* __restrict__ ei) {
    int e = blockIdx.x * blockDim.x + threadIdx.x;
    if (e < N_EDGES) {
        int s = edge_src(ei, e);
        int d = edge_dst(ei, e);
        int pos = atomicAdd(&g_cursor[d], 1);
        g_col[pos] = s;
        g_w[pos]   = g_dinv[s];
    }
}

// ---------------- 3. AX = norm-aggregate(X), 128 feats ----------------
__global__ void k_agg1(const float* __restrict__ X) {
    int i = blockIdx.x;
    int t = threadIdx.x;
    float di = g_dinv[i];
    int e0 = g_rowptr[i], e1 = g_rowptr[i + 1];
    float acc = 0.0f;
    for (int e = e0; e < e1; e++) {
        int s  = g_col[e];
        float a = g_w[e];
        acc += a * X[(size_t)s * NF + t];
    }
    float self = X[(size_t)i * NF + t];
    g_AX[(size_t)i * NF + t] = di * acc + di * di * self;
}

// ---------------- 4. H = relu(AX @ W1 + b1)  [50000,128]@[128,512] --------
__global__ void __launch_bounds__(256) k_gemm1(const float* __restrict__ W1,
                                               const float* __restrict__ b1) {
    __shared__ float As[64][68];
    __shared__ float Bs[64][64];
    const int m0 = blockIdx.x * 64;
    const int n0 = blockIdx.y * 64;
    const int tid = threadIdx.x;
    const int tx = tid & 15;
    const int ty = tid >> 4;

    float acc[4][4];
#pragma unroll
    for (int i = 0; i < 4; i++)
#pragma unroll
        for (int j = 0; j < 4; j++) acc[i][j] = 0.0f;

    for (int kk = 0; kk < NF; kk += 64) {
#pragma unroll
        for (int it = 0; it < 4; it++) {
            int idx = tid + it * 256;
            int r = idx >> 4;
            int c4 = idx & 15;
            int gr = m0 + r;
            float4 v = make_float4(0.f, 0.f, 0.f, 0.f);
            if (gr < N_NODES)
                v = *(const float4*)&g_AX[(size_t)gr * NF + kk + c4 * 4];
            *(float4*)&As[r][c4 * 4] = v;
        }
#pragma unroll
        for (int it = 0; it < 4; it++) {
            int idx = tid + it * 256;
            int r = idx >> 4;
            int c4 = idx & 15;
            *(float4*)&Bs[r][c4 * 4] =
                *(const float4*)&W1[(size_t)(kk + r) * NH + n0 + c4 * 4];
        }
        __syncthreads();

#pragma unroll
        for (int k = 0; k < 64; k++) {
            float4 b = *(const float4*)&Bs[k][tx * 4];
            float a0 = As[ty * 4 + 0][k];
            float a1 = As[ty * 4 + 1][k];
            float a2 = As[ty * 4 + 2][k];
            float a3 = As[ty * 4 + 3][k];
            acc[0][0] += a0 * b.x; acc[0][1] += a0 * b.y; acc[0][2] += a0 * b.z; acc[0][3] += a0 * b.w;
            acc[1][0] += a1 * b.x; acc[1][1] += a1 * b.y; acc[1][2] += a1 * b.z; acc[1][3] += a1 * b.w;
            acc[2][0] += a2 * b.x; acc[2][1] += a2 * b.y; acc[2][2] += a2 * b.z; acc[2][3] += a2 * b.w;
            acc[3][0] += a3 * b.x; acc[3][1] += a3 * b.y; acc[3][2] += a3 * b.z; acc[3][3] += a3 * b.w;
        }
        __syncthreads();
    }

    float4 bias = *(const float4*)&b1[n0 + tx * 4];
#pragma unroll
    for (int i = 0; i < 4; i++) {
        int row = m0 + ty * 4 + i;
        if (row < N_NODES) {
            float4 o;
            o.x = fmaxf(acc[i][0] + bias.x, 0.0f);
            o.y = fmaxf(acc[i][1] + bias.y, 0.0f);
            o.z = fmaxf(acc[i][2] + bias.z, 0.0f);
            o.w = fmaxf(acc[i][3] + bias.w, 0.0f);
            *(float4*)&g_H[(size_t)row * NH + n0 + tx * 4] = o;
        }
    }
}

// ---------------- 5. HW2 = H @ W2  [50000,512]@[512,2] ----------------
__global__ void k_gemm2(const float* __restrict__ W2) {
    int warp = threadIdx.x >> 5;
    int lane = threadIdx.x & 31;
    int i = blockIdx.x * 4 + warp;
    if (i >= N_NODES) return;
    float a0 = 0.f, a1 = 0.f;
    const float* hrow = &g_H[(size_t)i * NH];
#pragma unroll 4
    for (int k = lane; k < NH; k += 32) {
        float h = hrow[k];
        float w0 = W2[k * 2];
        float w1 = W2[k * 2 + 1];
        a0 += h * w0;
        a1 += h * w1;
    }
#pragma unroll
    for (int off = 16; off > 0; off >>= 1) {
        a0 += __shfl_xor_sync(0xFFFFFFFFu, a0, off);
        a1 += __shfl_xor_sync(0xFFFFFFFFu, a1, off);
    }
    if (lane == 0) g_HW2[i] = make_float2(a0, a1);
}

// ---------------- 6. aggregate layer2 + bias + softmax ----------------
__global__ void k_agg2(const float* __restrict__ b2, float* __restrict__ out) {
    int i = blockIdx.x * blockDim.x + threadIdx.x;
    if (i >= N_NODES) return;
    float di = g_dinv[i];
    int e0 = g_rowptr[i], e1 = g_rowptr[i + 1];
    float a0 = 0.f, a1 = 0.f;
    for (int e = e0; e < e1; e++) {
        int s = g_col[e];
        float w = g_w[e];
        float2 m = g_HW2[s];
        a0 += w * m.x;
        a1 += w * m.y;
    }
    float2 self = g_HW2[i];
    float l0 = di * a0 + di * di * self.x + b2[0];
    float l1 = di * a1 + di * di * self.y + b2[1];
    float mx = fmaxf(l0, l1);
    float e0f = __expf(l0 - mx);
    float e1f = __expf(l1 - mx);
    float inv = 1.0f / (e0f + e1f);
    out[(size_t)i * 2 + 0] = e0f * inv;
    out[(size_t)i * 2 + 1] = e1f * inv;
}

// ---------------- launch ----------------
extern "C" void kernel_launch(void* const* d_in, const int* in_sizes, int n_in,
                              void* d_out, int out_size) {
    const float* X  = (const float*)d_in[0];
    const void*  EI = d_in[1];
    const float* W1 = (const float*)d_in[2];
    const float* b1 = (const float*)d_in[3];
    const float* W2 = (const float*)d_in[4];
    const float* b2 = (const float*)d_in[5];
    float* out = (float*)d_out;

    (void)in_sizes; (void)n_in; (void)out_size;

    k_probe<<<1, 32>>>(EI);
    k_zero_cnt<<<(N_NODES + 255) / 256, 256>>>();
    k_count<<<(N_EDGES + 255) / 256, 256>>>(EI);
    k_dinv<<<(N_NODES + 255) / 256, 256>>>();
    k_scan<<<1, 1024>>>();
    k_scatter<<<(N_EDGES + 255) / 256, 256>>>(EI);
    k_agg1<<<N_NODES, NF>>>(X);
    dim3 g1((N_NODES + 63) / 64, NH / 64);
    k_gemm1<<<g1, 256>>>(W1, b1);
    k_gemm2<<<(N_NODES + 3) / 4, 128>>>(W2);
    k_agg2<<<(N_NODES + 127) / 128, 128>>>(b2, out);
}

// round 4
// speedup vs baseline: 1.2721x; 1.2721x over previous
#include <cuda_runtime.h>
#include <cuda_bf16.h>
#include <math.h>
#include <stdint.h>

#define N_NODES 50000
#define N_EDGES 800000
#define NF 128
#define NH 512

// ---------------- scratch (device globals) ----------------
__device__ float g_dinv[N_NODES];
__device__ int   g_cnt[N_NODES];
__device__ int   g_rowptr[N_NODES + 1];
__device__ int   g_cursor[N_NODES];
__device__ int   g_col[N_EDGES];
__device__ float g_w[N_EDGES];
__device__ __align__(16) __nv_bfloat16 g_AX_hi[(size_t)N_NODES * NF];
__device__ __align__(16) __nv_bfloat16 g_AX_lo[(size_t)N_NODES * NF];
__device__ __align__(16) __nv_bfloat16 g_W1T_hi[(size_t)NH * NF];
__device__ __align__(16) __nv_bfloat16 g_W1T_lo[(size_t)NH * NF];
__device__ float2 g_HW2p[8][N_NODES];   // per (n-block, warp-col) partials
__device__ float2 g_HW2[N_NODES];
__device__ int   g_is32;

__device__ __forceinline__ uint32_t smem_u32(const void* p) {
    uint32_t a;
    asm("{ .reg .u64 t; cvta.to.shared.u64 t, %1; cvt.u32.u64 %0, t; }" : "=r"(a) : "l"(p));
    return a;
}

// ---------------- 0. dtype probe ----------------
__global__ void k_probe(const void* __restrict__ ei) {
    if (threadIdx.x == 0 && blockIdx.x == 0) {
        const long long* p = (const long long*)ei;
        int bad = 0;
        for (int i = 0; i < 16; i++) {
            long long v = p[i];
            if (v < 0 || v >= (long long)N_NODES) bad = 1;
        }
        g_is32 = bad;
    }
}
__device__ __forceinline__ int clampi(int v) {
    v = v < 0 ? 0 : v;
    return v >= N_NODES ? N_NODES - 1 : v;
}
__device__ __forceinline__ int edge_src(const void* ei, int e) {
    int v = g_is32 ? ((const int*)ei)[e] : (int)((const long long*)ei)[e];
    return clampi(v);
}
__device__ __forceinline__ int edge_dst(const void* ei, int e) {
    int v = g_is32 ? ((const int*)ei)[N_EDGES + e] : (int)((const long long*)ei)[N_EDGES + e];
    return clampi(v);
}

// ---------------- 1. degree / dinv ----------------
__global__ void k_zero_cnt() {
    int i = blockIdx.x * blockDim.x + threadIdx.x;
    if (i < N_NODES) g_cnt[i] = 0;
}
__global__ void k_count(const void* __restrict__ ei) {
    int e = blockIdx.x * blockDim.x + threadIdx.x;
    if (e < N_EDGES) atomicAdd(&g_cnt[edge_dst(ei, e)], 1);
}
__global__ void k_dinv() {
    int i = blockIdx.x * blockDim.x + threadIdx.x;
    if (i < N_NODES) g_dinv[i] = rsqrtf((float)g_cnt[i] + 1.0f);
}

// ---------------- 2. CSR build ----------------
__global__ void k_scan() {
    __shared__ int sums[1024];
    const int tid = threadIdx.x;
    const int CH = (N_NODES + 1023) / 1024;
    int base = tid * CH;
    int s = 0;
    for (int i = 0; i < CH; i++) {
        int idx = base + i;
        if (idx < N_NODES) s += g_cnt[idx];
    }
    sums[tid] = s;
    __syncthreads();
    for (int off = 1; off < 1024; off <<= 1) {
        int v = (tid >= off) ? sums[tid - off] : 0;
        __syncthreads();
        sums[tid] += v;
        __syncthreads();
    }
    int run = (tid == 0) ? 0 : sums[tid - 1];
    for (int i = 0; i < CH; i++) {
        int idx = base + i;
        if (idx < N_NODES) {
            g_rowptr[idx] = run;
            g_cursor[idx] = run;
            run += g_cnt[idx];
        }
    }
    if (tid == 1023) g_rowptr[N_NODES] = sums[1023];
}
__global__ void k_scatter(const void* __restrict__ ei) {
    int e = blockIdx.x * blockDim.x + threadIdx.x;
    if (e < N_EDGES) {
        int s = edge_src(ei, e);
        int d = edge_dst(ei, e);
        int pos = atomicAdd(&g_cursor[d], 1);
        g_col[pos] = s;
        g_w[pos] = g_dinv[s];
    }
}

// ---------------- 3. W1 -> transposed bf16 hi/lo ----------------
__global__ void k_prep_w1t(const float* __restrict__ W1) {
    int idx = blockIdx.x * blockDim.x + threadIdx.x;
    if (idx >= NH * NF) return;
    int n = idx >> 7;
    int k = idx & 127;
    float v = W1[(size_t)k * NH + n];
    __nv_bfloat16 hi = __float2bfloat16_rn(v);
    __nv_bfloat16 lo = __float2bfloat16_rn(v - __bfloat162float(hi));
    g_W1T_hi[idx] = hi;
    g_W1T_lo[idx] = lo;
}

// ---------------- 4. AX = norm-aggregate(X) -> bf16 hi/lo ----------------
__global__ void k_agg1(const float* __restrict__ X) {
    int i = blockIdx.x;
    int t = threadIdx.x;
    float di = g_dinv[i];
    int e0 = g_rowptr[i], e1 = g_rowptr[i + 1];
    float acc = 0.0f;
    for (int e = e0; e < e1; e++) {
        int s = g_col[e];
        float a = g_w[e];
        acc += a * X[(size_t)s * NF + t];
    }
    float self = X[(size_t)i * NF + t];
    float v = di * acc + di * di * self;
    __nv_bfloat16 hi = __float2bfloat16_rn(v);
    __nv_bfloat16 lo = __float2bfloat16_rn(v - __bfloat162float(hi));
    size_t o = (size_t)i * NF + t;
    g_AX_hi[o] = hi;
    g_AX_lo[o] = lo;
}

// ---------------- 5. fused GEMM1 (mma.sync bf16) + bias + relu + W2 -------
// block tile 128x128, 8 warps (4m x 2n), warp tile 32x64, full K=128 in smem
#define SM_STRIDE 136      // bf16 elements per smem row (272 B = 17 x 16B)
#define OFF_A_HI 0
#define OFF_A_LO (OFF_A_HI + 128 * SM_STRIDE * 2)
#define OFF_B_HI (OFF_A_LO + 128 * SM_STRIDE * 2)
#define OFF_B_LO (OFF_B_HI + 128 * SM_STRIDE * 2)
#define OFF_B1   (OFF_B_LO + 128 * SM_STRIDE * 2)
#define OFF_W2X  (OFF_B1  + 512)
#define OFF_W2Y  (OFF_W2X + 512)
#define SMEM_BYTES (OFF_W2Y + 512)

#define LDMX4(r0, r1, r2, r3, addr) \
    asm volatile("ldmatrix.sync.aligned.m8n8.x4.shared.b16 {%0,%1,%2,%3}, [%4];" \
        : "=r"(r0), "=r"(r1), "=r"(r2), "=r"(r3) : "r"(addr))

#define MMA16816(d, a, b) \
    asm volatile("mma.sync.aligned.m16n8k16.row.col.f32.bf16.bf16.f32 " \
        "{%0,%1,%2,%3}, {%4,%5,%6,%7}, {%8,%9}, {%0,%1,%2,%3};" \
        : "+f"((d)[0]), "+f"((d)[1]), "+f"((d)[2]), "+f"((d)[3]) \
        : "r"((a)[0]), "r"((a)[1]), "r"((a)[2]), "r"((a)[3]), "r"((b)[0]), "r"((b)[1]))

__global__ void __launch_bounds__(256) k_gemm1_mma(const float* __restrict__ b1,
                                                   const float* __restrict__ W2) {
    extern __shared__ char smem[];
    const uint32_t sb = smem_u32(smem);
    const int tid  = threadIdx.x;
    const int lane = tid & 31;
    const int wid  = tid >> 5;
    const int wm   = wid & 3;      // warp m index (0..3) -> rows wm*32..+31
    const int wn   = wid >> 2;     // warp n index (0..1) -> cols wn*64..+63
    const int m0   = blockIdx.x * 128;
    const int n0   = blockIdx.y * 128;

    // ---- load A tiles (hi/lo), 128 rows x 128 bf16, padded stride ----
    {
        int row  = tid >> 1;
        int half = tid & 1;
        int gr = m0 + row;
        bool ok = gr < N_NODES;
        const uint4* srcH = (const uint4*)&g_AX_hi[(size_t)gr * NF + half * 64];
        const uint4* srcL = (const uint4*)&g_AX_lo[(size_t)gr * NF + half * 64];
        uint4 z = make_uint4(0, 0, 0, 0);
        char* dH = smem + OFF_A_HI + row * (SM_STRIDE * 2) + half * 128;
        char* dL = smem + OFF_A_LO + row * (SM_STRIDE * 2) + half * 128;
#pragma unroll
        for (int i = 0; i < 8; i++) {
            ((uint4*)dH)[i] = ok ? srcH[i] : z;
            ((uint4*)dL)[i] = ok ? srcL[i] : z;
        }
    }
    // ---- load B tiles (hi/lo): rows = n (0..127), cols = k ----
    {
        int row  = tid >> 1;
        int half = tid & 1;
        const uint4* srcH = (const uint4*)&g_W1T_hi[(size_t)(n0 + row) * NF + half * 64];
        const uint4* srcL = (const uint4*)&g_W1T_lo[(size_t)(n0 + row) * NF + half * 64];
        char* dH = smem + OFF_B_HI + row * (SM_STRIDE * 2) + half * 128;
        char* dL = smem + OFF_B_LO + row * (SM_STRIDE * 2) + half * 128;
#pragma unroll
        for (int i = 0; i < 8; i++) {
            ((uint4*)dH)[i] = srcH[i];
            ((uint4*)dL)[i] = srcL[i];
        }
    }
    // ---- epilogue constants ----
    if (tid < 128) {
        int ng = n0 + tid;
        ((float*)(smem + OFF_B1))[tid]  = b1[ng];
        ((float*)(smem + OFF_W2X))[tid] = W2[ng * 2 + 0];
        ((float*)(smem + OFF_W2Y))[tid] = W2[ng * 2 + 1];
    }
    __syncthreads();

    float d[2][8][4];
#pragma unroll
    for (int mt = 0; mt < 2; mt++)
#pragma unroll
        for (int nt = 0; nt < 8; nt++)
#pragma unroll
            for (int j = 0; j < 4; j++) d[mt][nt][j] = 0.0f;

    // ldmatrix lane addressing pieces
    const int a_row_in16 = lane & 15;
    const int a_k_half   = (lane >> 4) & 1;          // 0: k+0..7, 1: k+8..15
    const int b_n_off    = (lane & 7) + ((lane & 16) ? 8 : 0);
    const int b_k_half   = (lane & 8) ? 1 : 0;

#pragma unroll 1
    for (int k0 = 0; k0 < 128; k0 += 16) {
        uint32_t ah[2][4], al[2][4];
#pragma unroll
        for (int mt = 0; mt < 2; mt++) {
            int r = wm * 32 + mt * 16 + a_row_in16;
            uint32_t col = (uint32_t)(k0 + a_k_half * 8) * 2;
            uint32_t adH = sb + OFF_A_HI + (uint32_t)r * (SM_STRIDE * 2) + col;
            uint32_t adL = sb + OFF_A_LO + (uint32_t)r * (SM_STRIDE * 2) + col;
            LDMX4(ah[mt][0], ah[mt][1], ah[mt][2], ah[mt][3], adH);
            LDMX4(al[mt][0], al[mt][1], al[mt][2], al[mt][3], adL);
        }
        uint32_t bh[8][2], bl[8][2];
#pragma unroll
        for (int np = 0; np < 4; np++) {          // pairs of n8 tiles
            int nrow = wn * 64 + np * 16 + b_n_off;
            uint32_t col = (uint32_t)(k0 + b_k_half * 8) * 2;
            uint32_t adH = sb + OFF_B_HI + (uint32_t)nrow * (SM_STRIDE * 2) + col;
            uint32_t adL = sb + OFF_B_LO + (uint32_t)nrow * (SM_STRIDE * 2) + col;
            uint32_t r0, r1, r2, r3;
            LDMX4(r0, r1, r2, r3, adH);
            bh[np * 2][0] = r0; bh[np * 2][1] = r1;
            bh[np * 2 + 1][0] = r2; bh[np * 2 + 1][1] = r3;
            LDMX4(r0, r1, r2, r3, adL);
            bl[np * 2][0] = r0; bl[np * 2][1] = r1;
            bl[np * 2 + 1][0] = r2; bl[np * 2 + 1][1] = r3;
        }
#pragma unroll
        for (int mt = 0; mt < 2; mt++) {
#pragma unroll
            for (int nt = 0; nt < 8; nt++) {
                MMA16816(d[mt][nt], ah[mt], bh[nt]);
                MMA16816(d[mt][nt], ah[mt], bl[nt]);
                MMA16816(d[mt][nt], al[mt], bh[nt]);
            }
        }
    }

    // ---- epilogue: bias + relu + contract with W2 ----
    const float* sB1  = (const float*)(smem + OFF_B1);
    const float* sW2x = (const float*)(smem + OFF_W2X);
    const float* sW2y = (const float*)(smem + OFF_W2Y);
    const int g = lane >> 2;
    const int q = lane & 3;
#pragma unroll
    for (int mt = 0; mt < 2; mt++) {
#pragma unroll
        for (int rh = 0; rh < 2; rh++) {
            float p0 = 0.f, p1 = 0.f;
#pragma unroll
            for (int nt = 0; nt < 8; nt++) {
#pragma unroll
                for (int j = 0; j < 2; j++) {
                    int col = wn * 64 + nt * 8 + q * 2 + j;
                    float v = d[mt][nt][rh * 2 + j] + sB1[col];
                    v = fmaxf(v, 0.0f);
                    p0 += v * sW2x[col];
                    p1 += v * sW2y[col];
                }
            }
            p0 += __shfl_xor_sync(0xFFFFFFFFu, p0, 1);
            p1 += __shfl_xor_sync(0xFFFFFFFFu, p1, 1);
            p0 += __shfl_xor_sync(0xFFFFFFFFu, p0, 2);
            p1 += __shfl_xor_sync(0xFFFFFFFFu, p1, 2);
            if (q == 0) {
                int row = m0 + wm * 32 + mt * 16 + rh * 8 + g;
                if (row < N_NODES)
                    g_HW2p[blockIdx.y * 2 + wn][row] = make_float2(p0, p1);
            }
        }
    }
}

// ---------------- 6. sum partials ----------------
__global__ void k_sum_hw2() {
    int i = blockIdx.x * blockDim.x + threadIdx.x;
    if (i >= N_NODES) return;
    float a0 = 0.f, a1 = 0.f;
#pragma unroll
    for (int p = 0; p < 8; p++) {
        float2 v = g_HW2p[p][i];
        a0 += v.x;
        a1 += v.y;
    }
    g_HW2[i] = make_float2(a0, a1);
}

// ---------------- 7. aggregate layer2 + bias + softmax ----------------
__global__ void k_agg2(const float* __restrict__ b2, float* __restrict__ out) {
    int i = blockIdx.x * blockDim.x + threadIdx.x;
    if (i >= N_NODES) return;
    float di = g_dinv[i];
    int e0 = g_rowptr[i], e1 = g_rowptr[i + 1];
    float a0 = 0.f, a1 = 0.f;
    for (int e = e0; e < e1; e++) {
        int s = g_col[e];
        float w = g_w[e];
        float2 m = g_HW2[s];
        a0 += w * m.x;
        a1 += w * m.y;
    }
    float2 self = g_HW2[i];
    float l0 = di * a0 + di * di * self.x + b2[0];
    float l1 = di * a1 + di * di * self.y + b2[1];
    float mx = fmaxf(l0, l1);
    float e0f = __expf(l0 - mx);
    float e1f = __expf(l1 - mx);
    float inv = 1.0f / (e0f + e1f);
    out[(size_t)i * 2 + 0] = e0f * inv;
    out[(size_t)i * 2 + 1] = e1f * inv;
}

// ---------------- launch ----------------
extern "C" void kernel_launch(void* const* d_in, const int* in_sizes, int n_in,
                              void* d_out, int out_size) {
    const float* X  = (const float*)d_in[0];
    const void*  EI = d_in[1];
    const float* W1 = (const float*)d_in[2];
    const float* b1 = (const float*)d_in[3];
    const float* W2 = (const float*)d_in[4];
    const float* b2 = (const float*)d_in[5];
    float* out = (float*)d_out;
    (void)in_sizes; (void)n_in; (void)out_size;

    cudaFuncSetAttribute(k_gemm1_mma, cudaFuncAttributeMaxDynamicSharedMemorySize, SMEM_BYTES);

    k_probe<<<1, 32>>>(EI);
    k_zero_cnt<<<(N_NODES + 255) / 256, 256>>>();
    k_count<<<(N_EDGES + 255) / 256, 256>>>(EI);
    k_dinv<<<(N_NODES + 255) / 256, 256>>>();
    k_scan<<<1, 1024>>>();
    k_scatter<<<(N_EDGES + 255) / 256, 256>>>(EI);
    k_prep_w1t<<<(NH * NF + 255) / 256, 256>>>(W1);
    k_agg1<<<N_NODES, NF>>>(X);
    dim3 g1((N_NODES + 127) / 128, 4);
    k_gemm1_mma<<<g1, 256, SMEM_BYTES>>>(b1, W2);
    k_sum_hw2<<<(N_NODES + 255) / 256, 256>>>();
    k_agg2<<<(N_NODES + 127) / 128, 128>>>(b2, out);
}

// round 5
// speedup vs baseline: 1.3481x; 1.0598x over previous
#include <cuda_runtime.h>
#include <cuda_bf16.h>
#include <math.h>
#include <stdint.h>

#define N_NODES 50000
#define N_EDGES 800000
#define NF 128
#define NH 512

// ---------------- scratch (device globals) ----------------
__device__ float g_dinv[N_NODES];
__device__ int   g_cnt[N_NODES];
__device__ int   g_rowptr[N_NODES + 1];
__device__ int   g_cursor[N_NODES];
__device__ int   g_col[N_EDGES];
__device__ __align__(16) float g_Xs[(size_t)N_NODES * NF];        // X * dinv
__device__ __align__(16) __nv_bfloat16 g_AX_hi[(size_t)N_NODES * NF];
__device__ __align__(16) __nv_bfloat16 g_AX_lo[(size_t)N_NODES * NF];
__device__ __align__(16) __nv_bfloat16 g_W1T_hi[(size_t)NH * NF];
__device__ __align__(16) __nv_bfloat16 g_W1T_lo[(size_t)NH * NF];
__device__ float2 g_HW2p[2][N_NODES];
__device__ float2 g_HW2[N_NODES];     // dinv-scaled
__device__ int   g_is32;

__device__ __forceinline__ uint32_t smem_u32(const void* p) {
    uint32_t a;
    asm("{ .reg .u64 t; cvta.to.shared.u64 t, %1; cvt.u32.u64 %0, t; }" : "=r"(a) : "l"(p));
    return a;
}
__device__ __forceinline__ void cp16(uint32_t dst, const void* src, int sz) {
    asm volatile("cp.async.cg.shared.global [%0], [%1], 16, %2;"
                 :: "r"(dst), "l"(src), "r"(sz));
}
#define CP_COMMIT() asm volatile("cp.async.commit_group;" ::: "memory")
#define CP_WAIT0()  asm volatile("cp.async.wait_group 0;" ::: "memory")

// ---------------- 0/1. probe + zero ----------------
__global__ void k_init(const void* __restrict__ ei) {
    int i = blockIdx.x * blockDim.x + threadIdx.x;
    if (i < N_NODES) g_cnt[i] = 0;
    if (i == 0) {
        const long long* p = (const long long*)ei;
        int bad = 0;
        for (int j = 0; j < 16; j++) {
            long long v = p[j];
            if (v < 0 || v >= (long long)N_NODES) bad = 1;
        }
        g_is32 = bad;
    }
}
__device__ __forceinline__ int clampi(int v) {
    v = v < 0 ? 0 : v;
    return v >= N_NODES ? N_NODES - 1 : v;
}
__device__ __forceinline__ int edge_src(const void* ei, int e) {
    int v = g_is32 ? ((const int*)ei)[e] : (int)((const long long*)ei)[e];
    return clampi(v);
}
__device__ __forceinline__ int edge_dst(const void* ei, int e) {
    int v = g_is32 ? ((const int*)ei)[N_EDGES + e] : (int)((const long long*)ei)[N_EDGES + e];
    return clampi(v);
}

__global__ void k_count(const void* __restrict__ ei) {
    int e = blockIdx.x * blockDim.x + threadIdx.x;
    if (e < N_EDGES) atomicAdd(&g_cnt[edge_dst(ei, e)], 1);
}

// ---------------- 2. scan + dinv ----------------
__global__ void k_scan_dinv() {
    __shared__ int sums[1024];
    const int tid = threadIdx.x;
    const int CH = (N_NODES + 1023) / 1024;
    int base = tid * CH;
    int s = 0;
    for (int i = 0; i < CH; i++) {
        int idx = base + i;
        if (idx < N_NODES) s += g_cnt[idx];
    }
    sums[tid] = s;
    __syncthreads();
    for (int off = 1; off < 1024; off <<= 1) {
        int v = (tid >= off) ? sums[tid - off] : 0;
        __syncthreads();
        sums[tid] += v;
        __syncthreads();
    }
    int run = (tid == 0) ? 0 : sums[tid - 1];
    for (int i = 0; i < CH; i++) {
        int idx = base + i;
        if (idx < N_NODES) {
            int c = g_cnt[idx];
            g_rowptr[idx] = run;
            g_cursor[idx] = run;
            g_dinv[idx] = rsqrtf((float)c + 1.0f);
            run += c;
        }
    }
    if (tid == 1023) g_rowptr[N_NODES] = sums[1023];
}

__global__ void k_scatter(const void* __restrict__ ei) {
    int e = blockIdx.x * blockDim.x + threadIdx.x;
    if (e < N_EDGES) {
        int s = edge_src(ei, e);
        int d = edge_dst(ei, e);
        int pos = atomicAdd(&g_cursor[d], 1);
        g_col[pos] = s;
    }
}

// ---------------- 3. Xs = X * dinv ----------------
__global__ void k_xs(const float* __restrict__ X) {
    int idx = blockIdx.x * blockDim.x + threadIdx.x;
    if (idx < N_NODES * NF) g_Xs[idx] = X[idx] * g_dinv[idx >> 7];
}

// ---------------- 4. W1 -> transposed bf16 hi/lo ----------------
__global__ void k_prep_w1t(const float* __restrict__ W1) {
    int idx = blockIdx.x * blockDim.x + threadIdx.x;
    if (idx >= NH * NF) return;
    int n = idx >> 7;
    int k = idx & 127;
    float v = W1[(size_t)k * NH + n];
    __nv_bfloat16 hi = __float2bfloat16_rn(v);
    __nv_bfloat16 lo = __float2bfloat16_rn(v - __bfloat162float(hi));
    g_W1T_hi[idx] = hi;
    g_W1T_lo[idx] = lo;
}

// ---------------- 5. AX aggregate (warp per node, float4) -> bf16 hi/lo ---
__global__ void __launch_bounds__(256) k_agg1() {
    int gw = (blockIdx.x * blockDim.x + threadIdx.x) >> 5;
    int lane = threadIdx.x & 31;
    if (gw >= N_NODES) return;
    int i = gw;
    int e0 = g_rowptr[i], e1 = g_rowptr[i + 1];
    float4 acc = make_float4(0.f, 0.f, 0.f, 0.f);
    int e = e0;
#pragma unroll 1
    for (; e + 2 <= e1; e += 2) {
        int s0 = g_col[e], s1 = g_col[e + 1];
        float4 v0 = ((const float4*)&g_Xs[(size_t)s0 * NF])[lane];
        float4 v1 = ((const float4*)&g_Xs[(size_t)s1 * NF])[lane];
        acc.x += v0.x + v1.x;
        acc.y += v0.y + v1.y;
        acc.z += v0.z + v1.z;
        acc.w += v0.w + v1.w;
    }
    if (e < e1) {
        int s0 = g_col[e];
        float4 v0 = ((const float4*)&g_Xs[(size_t)s0 * NF])[lane];
        acc.x += v0.x; acc.y += v0.y; acc.z += v0.z; acc.w += v0.w;
    }
    float4 self = ((const float4*)&g_Xs[(size_t)i * NF])[lane];
    float di = g_dinv[i];
    float v[4] = {di * (acc.x + self.x), di * (acc.y + self.y),
                  di * (acc.z + self.z), di * (acc.w + self.w)};
    __nv_bfloat16 h[4], l[4];
#pragma unroll
    for (int j = 0; j < 4; j++) {
        h[j] = __float2bfloat16_rn(v[j]);
        l[j] = __float2bfloat16_rn(v[j] - __bfloat162float(h[j]));
    }
    *(uint2*)&g_AX_hi[(size_t)i * NF + lane * 4] = *(uint2*)h;
    *(uint2*)&g_AX_lo[(size_t)i * NF + lane * 4] = *(uint2*)l;
}

// ---------------- 6. fused GEMM1 (mma.sync bf16, n-loop) + epilogue -------
#define SM_STRIDE 136
#define SMS (SM_STRIDE * 2)            // 272 B per row
#define TILE_B (128 * SMS)             // 34816 B
#define OFF_A_HI 0
#define OFF_A_LO TILE_B
#define OFF_B0   (2 * TILE_B)          // buf0: hi at +0, lo at +TILE_B
#define OFF_B1   (4 * TILE_B)
#define OFF_CB1  (6 * TILE_B)
#define OFF_CW2X (OFF_CB1 + 2048)
#define OFF_CW2Y (OFF_CW2X + 2048)
#define SMEM_BYTES (OFF_CW2Y + 2048)

#define LDMX4(r0, r1, r2, r3, addr) \
    asm volatile("ldmatrix.sync.aligned.m8n8.x4.shared.b16 {%0,%1,%2,%3}, [%4];" \
        : "=r"(r0), "=r"(r1), "=r"(r2), "=r"(r3) : "r"(addr))

#define MMA16816(d, a, b) \
    asm volatile("mma.sync.aligned.m16n8k16.row.col.f32.bf16.bf16.f32 " \
        "{%0,%1,%2,%3}, {%4,%5,%6,%7}, {%8,%9}, {%0,%1,%2,%3};" \
        : "+f"((d)[0]), "+f"((d)[1]), "+f"((d)[2]), "+f"((d)[3]) \
        : "r"((a)[0]), "r"((a)[1]), "r"((a)[2]), "r"((a)[3]), "r"((b)[0]), "r"((b)[1]))

__device__ __forceinline__ void load_B_async(uint32_t sb, int nb, int buf, int tid) {
    int row = tid >> 1;
    int half = tid & 1;
    const char* srcH = (const char*)&g_W1T_hi[(size_t)(nb * 128 + row) * NF + half * 64];
    const char* srcL = (const char*)&g_W1T_lo[(size_t)(nb * 128 + row) * NF + half * 64];
    uint32_t base = sb + (buf ? OFF_B1 : OFF_B0) + (uint32_t)row * SMS + half * 128;
#pragma unroll
    for (int i = 0; i < 8; i++) {
        cp16(base + i * 16, srcH + i * 16, 16);
        cp16(base + TILE_B + i * 16, srcL + i * 16, 16);
    }
}

__global__ void __launch_bounds__(256) k_gemm1_mma(const float* __restrict__ b1,
                                                   const float* __restrict__ W2) {
    extern __shared__ char smem[];
    const uint32_t sb = smem_u32(smem);
    const int tid  = threadIdx.x;
    const int lane = tid & 31;
    const int wid  = tid >> 5;
    const int wm   = wid & 3;
    const int wn   = wid >> 2;
    const int m0   = blockIdx.x * 128;

    // A tiles via cp.async (hi/lo)
    {
        int row = tid >> 1;
        int half = tid & 1;
        int gr = m0 + row;
        int ok = (gr < N_NODES) ? 16 : 0;
        int grc = ok ? gr : 0;
        const char* srcH = (const char*)&g_AX_hi[(size_t)grc * NF + half * 64];
        const char* srcL = (const char*)&g_AX_lo[(size_t)grc * NF + half * 64];
        uint32_t dH = sb + OFF_A_HI + (uint32_t)row * SMS + half * 128;
        uint32_t dL = sb + OFF_A_LO + (uint32_t)row * SMS + half * 128;
#pragma unroll
        for (int i = 0; i < 8; i++) {
            cp16(dH + i * 16, srcH + i * 16, ok);
            cp16(dL + i * 16, srcL + i * 16, ok);
        }
    }
    load_B_async(sb, 0, 0, tid);
    // epilogue constants (512 cols)
    for (int i = tid; i < 512; i += 256) {
        ((float*)(smem + OFF_CB1))[i]  = b1[i];
        ((float*)(smem + OFF_CW2X))[i] = W2[i * 2 + 0];
        ((float*)(smem + OFF_CW2Y))[i] = W2[i * 2 + 1];
    }
    CP_COMMIT();
    CP_WAIT0();
    __syncthreads();

    const int a_row_in16 = lane & 15;
    const int a_k_half   = (lane >> 4) & 1;
    const int b_n_off    = (lane & 7) + ((lane & 16) ? 8 : 0);
    const int b_k_half   = (lane & 8) ? 1 : 0;
    const float* sB1  = (const float*)(smem + OFF_CB1);
    const float* sW2x = (const float*)(smem + OFF_CW2X);
    const float* sW2y = (const float*)(smem + OFF_CW2Y);
    const int g = lane >> 2;
    const int q = lane & 3;

    float p0[2][2], p1[2][2];
#pragma unroll
    for (int mt = 0; mt < 2; mt++)
#pragma unroll
        for (int rh = 0; rh < 2; rh++) { p0[mt][rh] = 0.f; p1[mt][rh] = 0.f; }

#pragma unroll 1
    for (int nb = 0; nb < 4; nb++) {
        if (nb < 3) { load_B_async(sb, nb + 1, (nb + 1) & 1, tid); CP_COMMIT(); }
        const uint32_t bbase = sb + ((nb & 1) ? OFF_B1 : OFF_B0);

        float d[2][8][4];
#pragma unroll
        for (int mt = 0; mt < 2; mt++)
#pragma unroll
            for (int nt = 0; nt < 8; nt++)
#pragma unroll
                for (int j = 0; j < 4; j++) d[mt][nt][j] = 0.0f;

#pragma unroll 1
        for (int k0 = 0; k0 < 128; k0 += 16) {
            uint32_t ah[2][4], al[2][4];
#pragma unroll
            for (int mt = 0; mt < 2; mt++) {
                int r = wm * 32 + mt * 16 + a_row_in16;
                uint32_t col = (uint32_t)(k0 + a_k_half * 8) * 2;
                LDMX4(ah[mt][0], ah[mt][1], ah[mt][2], ah[mt][3],
                      sb + OFF_A_HI + (uint32_t)r * SMS + col);
                LDMX4(al[mt][0], al[mt][1], al[mt][2], al[mt][3],
                      sb + OFF_A_LO + (uint32_t)r * SMS + col);
            }
            uint32_t bh[8][2], bl[8][2];
#pragma unroll
            for (int np = 0; np < 4; np++) {
                int nrow = wn * 64 + np * 16 + b_n_off;
                uint32_t col = (uint32_t)(k0 + b_k_half * 8) * 2;
                uint32_t r0, r1, r2, r3;
                LDMX4(r0, r1, r2, r3, bbase + (uint32_t)nrow * SMS + col);
                bh[np * 2][0] = r0; bh[np * 2][1] = r1;
                bh[np * 2 + 1][0] = r2; bh[np * 2 + 1][1] = r3;
                LDMX4(r0, r1, r2, r3, bbase + TILE_B + (uint32_t)nrow * SMS + col);
                bl[np * 2][0] = r0; bl[np * 2][1] = r1;
                bl[np * 2 + 1][0] = r2; bl[np * 2 + 1][1] = r3;
            }
#pragma unroll
            for (int mt = 0; mt < 2; mt++)
#pragma unroll
                for (int nt = 0; nt < 8; nt++) {
                    MMA16816(d[mt][nt], ah[mt], bh[nt]);
                    MMA16816(d[mt][nt], ah[mt], bl[nt]);
                    MMA16816(d[mt][nt], al[mt], bh[nt]);
                }
        }

        // contract this n-block into p
#pragma unroll
        for (int mt = 0; mt < 2; mt++)
#pragma unroll
            for (int rh = 0; rh < 2; rh++)
#pragma unroll
                for (int nt = 0; nt < 8; nt++)
#pragma unroll
                    for (int j = 0; j < 2; j++) {
                        int col = nb * 128 + wn * 64 + nt * 8 + q * 2 + j;
                        float v = d[mt][nt][rh * 2 + j] + sB1[col];
                        v = fmaxf(v, 0.0f);
                        p0[mt][rh] += v * sW2x[col];
                        p1[mt][rh] += v * sW2y[col];
                    }

        if (nb < 3) { CP_WAIT0(); __syncthreads(); }
    }

#pragma unroll
    for (int mt = 0; mt < 2; mt++)
#pragma unroll
        for (int rh = 0; rh < 2; rh++) {
            float a = p0[mt][rh], b = p1[mt][rh];
            a += __shfl_xor_sync(0xFFFFFFFFu, a, 1);
            b += __shfl_xor_sync(0xFFFFFFFFu, b, 1);
            a += __shfl_xor_sync(0xFFFFFFFFu, a, 2);
            b += __shfl_xor_sync(0xFFFFFFFFu, b, 2);
            if (q == 0) {
                int row = m0 + wm * 32 + mt * 16 + rh * 8 + g;
                if (row < N_NODES) g_HW2p[wn][row] = make_float2(a, b);
            }
        }
}

// ---------------- 7. sum partials (+ fold dinv) ----------------
__global__ void k_sum_hw2() {
    int i = blockIdx.x * blockDim.x + threadIdx.x;
    if (i >= N_NODES) return;
    float2 a = g_HW2p[0][i], b = g_HW2p[1][i];
    float di = g_dinv[i];
    g_HW2[i] = make_float2(di * (a.x + b.x), di * (a.y + b.y));
}

// ---------------- 8. aggregate layer2 + bias + softmax ----------------
__global__ void k_agg2(const float* __restrict__ b2, float* __restrict__ out) {
    int i = blockIdx.x * blockDim.x + threadIdx.x;
    if (i >= N_NODES) return;
    float di = g_dinv[i];
    int e0 = g_rowptr[i], e1 = g_rowptr[i + 1];
    float a0 = 0.f, a1 = 0.f;
    for (int e = e0; e < e1; e++) {
        float2 m = g_HW2[g_col[e]];
        a0 += m.x;
        a1 += m.y;
    }
    float2 self = g_HW2[i];
    float l0 = di * (a0 + self.x) + b2[0];
    float l1 = di * (a1 + self.y) + b2[1];
    float mx = fmaxf(l0, l1);
    float e0f = __expf(l0 - mx);
    float e1f = __expf(l1 - mx);
    float inv = 1.0f / (e0f + e1f);
    out[(size_t)i * 2 + 0] = e0f * inv;
    out[(size_t)i * 2 + 1] = e1f * inv;
}

// ---------------- launch ----------------
extern "C" void kernel_launch(void* const* d_in, const int* in_sizes, int n_in,
                              void* d_out, int out_size) {
    const float* X  = (const float*)d_in[0];
    const void*  EI = d_in[1];
    const float* W1 = (const float*)d_in[2];
    const float* b1 = (const float*)d_in[3];
    const float* W2 = (const float*)d_in[4];
    const float* b2 = (const float*)d_in[5];
    float* out = (float*)d_out;
    (void)in_sizes; (void)n_in; (void)out_size;

    cudaFuncSetAttribute(k_gemm1_mma, cudaFuncAttributeMaxDynamicSharedMemorySize, SMEM_BYTES);

    k_init<<<(N_NODES + 255) / 256, 256>>>(EI);
    k_count<<<(N_EDGES + 255) / 256, 256>>>(EI);
    k_scan_dinv<<<1, 1024>>>();
    k_scatter<<<(N_EDGES + 255) / 256, 256>>>(EI);
    k_xs<<<(N_NODES * NF + 255) / 256, 256>>>(X);
    k_prep_w1t<<<(NH * NF + 255) / 256, 256>>>(W1);
    k_agg1<<<(N_NODES * 32 + 255) / 256, 256>>>();
    k_gemm1_mma<<<(N_NODES + 127) / 128, 256, SMEM_BYTES>>>(b1, W2);
    k_sum_hw2<<<(N_NODES + 255) / 256, 256>>>();
    k_agg2<<<(N_NODES + 127) / 128, 128>>>(b2, out);
}

// round 6
// speedup vs baseline: 1.5976x; 1.1851x over previous
#include <cuda_runtime.h>
#include <cuda_fp16.h>
#include <math.h>
#include <stdint.h>

#define N_NODES 50000
#define N_EDGES 800000
#define NF 128
#define NH 512

// ---------------- scratch (device globals) ----------------
__device__ float g_dinv[N_NODES];
__device__ int   g_cnt[N_NODES];
__device__ int   g_rowptr[N_NODES + 1];
__device__ int   g_cursor[N_NODES];
__device__ int   g_col[N_EDGES];
__device__ __align__(16) __half g_AX_hi[(size_t)N_NODES * NF];
__device__ __align__(16) __half g_AX_lo[(size_t)N_NODES * NF];
__device__ __align__(16) __half g_W1T_h[(size_t)NH * NF];
__device__ float2 g_HW2[N_NODES];     // dinv-scaled
__device__ int   g_is32;

__device__ __forceinline__ uint32_t smem_u32(const void* p) {
    uint32_t a;
    asm("{ .reg .u64 t; cvta.to.shared.u64 t, %1; cvt.u32.u64 %0, t; }" : "=r"(a) : "l"(p));
    return a;
}
__device__ __forceinline__ void cp16(uint32_t dst, const void* src, int sz) {
    asm volatile("cp.async.cg.shared.global [%0], [%1], 16, %2;"
                 :: "r"(dst), "l"(src), "r"(sz));
}
#define CP_COMMIT() asm volatile("cp.async.commit_group;" ::: "memory")
#define CP_WAIT0()  asm volatile("cp.async.wait_group 0;" ::: "memory")

// ---------------- 0/1. probe + zero ----------------
__global__ void k_init(const void* __restrict__ ei) {
    int i = blockIdx.x * blockDim.x + threadIdx.x;
    if (i < N_NODES) g_cnt[i] = 0;
    if (i == 0) {
        const long long* p = (const long long*)ei;
        int bad = 0;
        for (int j = 0; j < 16; j++) {
            long long v = p[j];
            if (v < 0 || v >= (long long)N_NODES) bad = 1;
        }
        g_is32 = bad;
    }
}
__device__ __forceinline__ int clampi(int v) {
    v = v < 0 ? 0 : v;
    return v >= N_NODES ? N_NODES - 1 : v;
}
__device__ __forceinline__ int edge_src(const void* ei, int e) {
    int v = g_is32 ? ((const int*)ei)[e] : (int)((const long long*)ei)[e];
    return clampi(v);
}
__device__ __forceinline__ int edge_dst(const void* ei, int e) {
    int v = g_is32 ? ((const int*)ei)[N_EDGES + e] : (int)((const long long*)ei)[N_EDGES + e];
    return clampi(v);
}

__global__ void k_count(const void* __restrict__ ei) {
    int e = blockIdx.x * blockDim.x + threadIdx.x;
    if (e < N_EDGES) atomicAdd(&g_cnt[edge_dst(ei, e)], 1);
}

// ---------------- 2. scan + dinv ----------------
__global__ void k_scan_dinv() {
    __shared__ int sums[1024];
    const int tid = threadIdx.x;
    const int CH = (N_NODES + 1023) / 1024;
    int base = tid * CH;
    int s = 0;
    for (int i = 0; i < CH; i++) {
        int idx = base + i;
        if (idx < N_NODES) s += g_cnt[idx];
    }
    sums[tid] = s;
    __syncthreads();
    for (int off = 1; off < 1024; off <<= 1) {
        int v = (tid >= off) ? sums[tid - off] : 0;
        __syncthreads();
        sums[tid] += v;
        __syncthreads();
    }
    int run = (tid == 0) ? 0 : sums[tid - 1];
    for (int i = 0; i < CH; i++) {
        int idx = base + i;
        if (idx < N_NODES) {
            int c = g_cnt[idx];
            g_rowptr[idx] = run;
            g_cursor[idx] = run;
            g_dinv[idx] = rsqrtf((float)c + 1.0f);
            run += c;
        }
    }
    if (tid == 1023) g_rowptr[N_NODES] = sums[1023];
}

__global__ void k_scatter(const void* __restrict__ ei) {
    int e = blockIdx.x * blockDim.x + threadIdx.x;
    if (e < N_EDGES) {
        int s = edge_src(ei, e);
        int d = edge_dst(ei, e);
        int pos = atomicAdd(&g_cursor[d], 1);
        g_col[pos] = s;
    }
}

// ---------------- 3. W1 -> transposed fp16 ----------------
__global__ void k_prep_w1t(const float* __restrict__ W1) {
    int idx = blockIdx.x * blockDim.x + threadIdx.x;
    if (idx >= NH * NF) return;
    int n = idx >> 7;
    int k = idx & 127;
    g_W1T_h[idx] = __float2half_rn(W1[(size_t)k * NH + n]);
}

// ---------------- 4. AX aggregate (warp per node) -> fp16 hi/lo ----------
__global__ void __launch_bounds__(256) k_agg1(const float* __restrict__ X) {
    int gw = (blockIdx.x * blockDim.x + threadIdx.x) >> 5;
    int lane = threadIdx.x & 31;
    if (gw >= N_NODES) return;
    int i = gw;
    int e0 = g_rowptr[i], e1 = g_rowptr[i + 1];
    float4 acc = make_float4(0.f, 0.f, 0.f, 0.f);
    int e = e0;
#pragma unroll 1
    for (; e + 2 <= e1; e += 2) {
        int s0 = g_col[e], s1 = g_col[e + 1];
        float w0 = g_dinv[s0], w1 = g_dinv[s1];
        float4 v0 = ((const float4*)&X[(size_t)s0 * NF])[lane];
        float4 v1 = ((const float4*)&X[(size_t)s1 * NF])[lane];
        acc.x += w0 * v0.x + w1 * v1.x;
        acc.y += w0 * v0.y + w1 * v1.y;
        acc.z += w0 * v0.z + w1 * v1.z;
        acc.w += w0 * v0.w + w1 * v1.w;
    }
    if (e < e1) {
        int s0 = g_col[e];
        float w0 = g_dinv[s0];
        float4 v0 = ((const float4*)&X[(size_t)s0 * NF])[lane];
        acc.x += w0 * v0.x; acc.y += w0 * v0.y;
        acc.z += w0 * v0.z; acc.w += w0 * v0.w;
    }
    float di = g_dinv[i];
    float4 self = ((const float4*)&X[(size_t)i * NF])[lane];
    float v[4] = {di * (acc.x + di * self.x), di * (acc.y + di * self.y),
                  di * (acc.z + di * self.z), di * (acc.w + di * self.w)};
    __half h[4], l[4];
#pragma unroll
    for (int j = 0; j < 4; j++) {
        h[j] = __float2half_rn(v[j]);
        l[j] = __float2half_rn(v[j] - __half2float(h[j]));
    }
    *(uint2*)&g_AX_hi[(size_t)i * NF + lane * 4] = *(uint2*)h;
    *(uint2*)&g_AX_lo[(size_t)i * NF + lane * 4] = *(uint2*)l;
}

// ---------------- 5. fused GEMM1 (mma.sync fp16 2-term) + epilogue -------
#define SM_STRIDE 136
#define SMS (SM_STRIDE * 2)            // 272 B per row
#define TILE_B (128 * SMS)             // 34816 B
#define OFF_A_HI 0
#define OFF_A_LO TILE_B
#define OFF_B0   (2 * TILE_B)
#define OFF_B1   (3 * TILE_B)
#define OFF_CB1  (4 * TILE_B)
#define OFF_CW2X (OFF_CB1 + 2048)
#define OFF_CW2Y (OFF_CW2X + 2048)
#define OFF_RED  (OFF_CW2Y + 2048)
#define SMEM_BYTES (OFF_RED + 1024)

#define LDMX4(r0, r1, r2, r3, addr) \
    asm volatile("ldmatrix.sync.aligned.m8n8.x4.shared.b16 {%0,%1,%2,%3}, [%4];" \
        : "=r"(r0), "=r"(r1), "=r"(r2), "=r"(r3) : "r"(addr))

#define MMA16816(d, a, b) \
    asm volatile("mma.sync.aligned.m16n8k16.row.col.f32.f16.f16.f32 " \
        "{%0,%1,%2,%3}, {%4,%5,%6,%7}, {%8,%9}, {%0,%1,%2,%3};" \
        : "+f"((d)[0]), "+f"((d)[1]), "+f"((d)[2]), "+f"((d)[3]) \
        : "r"((a)[0]), "r"((a)[1]), "r"((a)[2]), "r"((a)[3]), "r"((b)[0]), "r"((b)[1]))

__device__ __forceinline__ void load_B_async(uint32_t sb, int nb, int buf, int tid) {
    int row = tid >> 1;
    int half = tid & 1;
    const char* src = (const char*)&g_W1T_h[(size_t)(nb * 128 + row) * NF + half * 64];
    uint32_t base = sb + (buf ? OFF_B1 : OFF_B0) + (uint32_t)row * SMS + half * 128;
#pragma unroll
    for (int i = 0; i < 8; i++) cp16(base + i * 16, src + i * 16, 16);
}

__global__ void __launch_bounds__(256) k_gemm1_mma(const float* __restrict__ b1,
                                                   const float* __restrict__ W2) {
    extern __shared__ char smem[];
    const uint32_t sb = smem_u32(smem);
    const int tid  = threadIdx.x;
    const int lane = tid & 31;
    const int wid  = tid >> 5;
    const int wm   = wid & 3;
    const int wn   = wid >> 2;
    const int m0   = blockIdx.x * 128;

    // A tiles via cp.async (hi/lo)
    {
        int row = tid >> 1;
        int half = tid & 1;
        int gr = m0 + row;
        int ok = (gr < N_NODES) ? 16 : 0;
        int grc = (gr < N_NODES) ? gr : 0;
        const char* srcH = (const char*)&g_AX_hi[(size_t)grc * NF + half * 64];
        const char* srcL = (const char*)&g_AX_lo[(size_t)grc * NF + half * 64];
        uint32_t dH = sb + OFF_A_HI + (uint32_t)row * SMS + half * 128;
        uint32_t dL = sb + OFF_A_LO + (uint32_t)row * SMS + half * 128;
#pragma unroll
        for (int i = 0; i < 8; i++) {
            cp16(dH + i * 16, srcH + i * 16, ok);
            cp16(dL + i * 16, srcL + i * 16, ok);
        }
    }
    load_B_async(sb, 0, 0, tid);
    for (int i = tid; i < 512; i += 256) {
        ((float*)(smem + OFF_CB1))[i]  = b1[i];
        ((float*)(smem + OFF_CW2X))[i] = W2[i * 2 + 0];
        ((float*)(smem + OFF_CW2Y))[i] = W2[i * 2 + 1];
    }
    CP_COMMIT();
    CP_WAIT0();
    __syncthreads();

    const int a_row_in16 = lane & 15;
    const int a_k_half   = (lane >> 4) & 1;
    const int b_n_off    = (lane & 7) + ((lane & 16) ? 8 : 0);
    const int b_k_half   = (lane & 8) ? 1 : 0;
    const float* sB1  = (const float*)(smem + OFF_CB1);
    const float* sW2x = (const float*)(smem + OFF_CW2X);
    const float* sW2y = (const float*)(smem + OFF_CW2Y);
    const int g = lane >> 2;
    const int q = lane & 3;

    float p0[2][2], p1[2][2];
#pragma unroll
    for (int mt = 0; mt < 2; mt++)
#pragma unroll
        for (int rh = 0; rh < 2; rh++) { p0[mt][rh] = 0.f; p1[mt][rh] = 0.f; }

#pragma unroll 1
    for (int nb = 0; nb < 4; nb++) {
        if (nb < 3) { load_B_async(sb, nb + 1, (nb + 1) & 1, tid); CP_COMMIT(); }
        const uint32_t bbase = sb + ((nb & 1) ? OFF_B1 : OFF_B0);

        float d[2][8][4];
#pragma unroll
        for (int mt = 0; mt < 2; mt++)
#pragma unroll
            for (int nt = 0; nt < 8; nt++)
#pragma unroll
                for (int j = 0; j < 4; j++) d[mt][nt][j] = 0.0f;

#pragma unroll 1
        for (int k0 = 0; k0 < 128; k0 += 16) {
            uint32_t ah[2][4], al[2][4];
#pragma unroll
            for (int mt = 0; mt < 2; mt++) {
                int r = wm * 32 + mt * 16 + a_row_in16;
                uint32_t col = (uint32_t)(k0 + a_k_half * 8) * 2;
                LDMX4(ah[mt][0], ah[mt][1], ah[mt][2], ah[mt][3],
                      sb + OFF_A_HI + (uint32_t)r * SMS + col);
                LDMX4(al[mt][0], al[mt][1], al[mt][2], al[mt][3],
                      sb + OFF_A_LO + (uint32_t)r * SMS + col);
            }
            uint32_t bh[8][2];
#pragma unroll
            for (int np = 0; np < 4; np++) {
                int nrow = wn * 64 + np * 16 + b_n_off;
                uint32_t col = (uint32_t)(k0 + b_k_half * 8) * 2;
                uint32_t r0, r1, r2, r3;
                LDMX4(r0, r1, r2, r3, bbase + (uint32_t)nrow * SMS + col);
                bh[np * 2][0] = r0; bh[np * 2][1] = r1;
                bh[np * 2 + 1][0] = r2; bh[np * 2 + 1][1] = r3;
            }
#pragma unroll
            for (int mt = 0; mt < 2; mt++)
#pragma unroll
                for (int nt = 0; nt < 8; nt++) {
                    MMA16816(d[mt][nt], ah[mt], bh[nt]);
                    MMA16816(d[mt][nt], al[mt], bh[nt]);
                }
        }

#pragma unroll
        for (int mt = 0; mt < 2; mt++)
#pragma unroll
            for (int rh = 0; rh < 2; rh++)
#pragma unroll
                for (int nt = 0; nt < 8; nt++)
#pragma unroll
                    for (int j = 0; j < 2; j++) {
                        int col = nb * 128 + wn * 64 + nt * 8 + q * 2 + j;
                        float v = d[mt][nt][rh * 2 + j] + sB1[col];
                        v = fmaxf(v, 0.0f);
                        p0[mt][rh] += v * sW2x[col];
                        p1[mt][rh] += v * sW2y[col];
                    }

        if (nb < 3) { CP_WAIT0(); __syncthreads(); }
    }

    // reduce within warp (q-lanes), then across wn through smem
    float pr0[2][2], pr1[2][2];
#pragma unroll
    for (int mt = 0; mt < 2; mt++)
#pragma unroll
        for (int rh = 0; rh < 2; rh++) {
            float a = p0[mt][rh], b = p1[mt][rh];
            a += __shfl_xor_sync(0xFFFFFFFFu, a, 1);
            b += __shfl_xor_sync(0xFFFFFFFFu, b, 1);
            a += __shfl_xor_sync(0xFFFFFFFFu, a, 2);
            b += __shfl_xor_sync(0xFFFFFFFFu, b, 2);
            pr0[mt][rh] = a; pr1[mt][rh] = b;
        }
    float2* red = (float2*)(smem + OFF_RED);
    __syncthreads();
    if (wn == 1 && q == 0) {
#pragma unroll
        for (int mt = 0; mt < 2; mt++)
#pragma unroll
            for (int rh = 0; rh < 2; rh++) {
                int lr = wm * 32 + mt * 16 + rh * 8 + g;
                red[lr] = make_float2(pr0[mt][rh], pr1[mt][rh]);
            }
    }
    __syncthreads();
    if (wn == 0 && q == 0) {
#pragma unroll
        for (int mt = 0; mt < 2; mt++)
#pragma unroll
            for (int rh = 0; rh < 2; rh++) {
                int lr = wm * 32 + mt * 16 + rh * 8 + g;
                int row = m0 + lr;
                if (row < N_NODES) {
                    float2 o = red[lr];
                    float di = g_dinv[row];
                    g_HW2[row] = make_float2(di * (pr0[mt][rh] + o.x),
                                             di * (pr1[mt][rh] + o.y));
                }
            }
    }
}

// ---------------- 6. aggregate layer2 + bias + softmax ----------------
__global__ void k_agg2(const float* __restrict__ b2, float* __restrict__ out) {
    int i = blockIdx.x * blockDim.x + threadIdx.x;
    if (i >= N_NODES) return;
    float di = g_dinv[i];
    int e0 = g_rowptr[i], e1 = g_rowptr[i + 1];
    float a0 = 0.f, a1 = 0.f;
    for (int e = e0; e < e1; e++) {
        float2 m = g_HW2[g_col[e]];
        a0 += m.x;
        a1 += m.y;
    }
    float2 self = g_HW2[i];
    float l0 = di * (a0 + self.x) + b2[0];
    float l1 = di * (a1 + self.y) + b2[1];
    float mx = fmaxf(l0, l1);
    float e0f = __expf(l0 - mx);
    float e1f = __expf(l1 - mx);
    float inv = 1.0f / (e0f + e1f);
    out[(size_t)i * 2 + 0] = e0f * inv;
    out[(size_t)i * 2 + 1] = e1f * inv;
}

// ---------------- launch ----------------
extern "C" void kernel_launch(void* const* d_in, const int* in_sizes, int n_in,
                              void* d_out, int out_size) {
    const float* X  = (const float*)d_in[0];
    const void*  EI = d_in[1];
    const float* W1 = (const float*)d_in[2];
    const float* b1 = (const float*)d_in[3];
    const float* W2 = (const float*)d_in[4];
    const float* b2 = (const float*)d_in[5];
    float* out = (float*)d_out;
    (void)in_sizes; (void)n_in; (void)out_size;

    cudaFuncSetAttribute(k_gemm1_mma, cudaFuncAttributeMaxDynamicSharedMemorySize, SMEM_BYTES);

    k_init<<<(N_NODES + 255) / 256, 256>>>(EI);
    k_count<<<(N_EDGES + 255) / 256, 256>>>(EI);
    k_scan_dinv<<<1, 1024>>>();
    k_scatter<<<(N_EDGES + 255) / 256, 256>>>(EI);
    k_prep_w1t<<<(NH * NF + 255) / 256, 256>>>(W1);
    k_agg1<<<(N_NODES * 32 + 255) / 256, 256>>>(X);
    k_gemm1_mma<<<(N_NODES + 127) / 128, 256, SMEM_BYTES>>>(b1, W2);
    k_agg2<<<(N_NODES + 127) / 128, 128>>>(b2, out);
}